// round 2
// baseline (speedup 1.0000x reference)
#include <cuda_runtime.h>
#include <math_constants.h>

// Per-row max of heads 1..6 (overwritten every call -> no init kernel needed)
#define MAX_ROWS 65536
__device__ float g_blockmax[MAX_ROWS];

// One block per row, 224 threads = exactly 7 warps. Warp h scans head h's row:
// top-2 + target value. Warps 0..5 contribute row-max to g_blockmax[row].
__global__ __launch_bounds__(224) void margin_softmax_kernel(
    const float* __restrict__ o1, const float* __restrict__ o2,
    const float* __restrict__ o3, const float* __restrict__ o4,
    const float* __restrict__ o5, const float* __restrict__ o6,
    const float* __restrict__ mimic,
    const int* __restrict__ targets,
    float* __restrict__ out_thresh,   // [N,7]
    int C)
{
    const int row  = blockIdx.x;
    const int wid  = threadIdx.x >> 5;   // 0..6
    const int lane = threadIdx.x & 31;

    __shared__ float s_margin[7];
    __shared__ float s_top1[7];

    const float* heads[7] = {o1, o2, o3, o4, o5, o6, mimic};
    const float* p = heads[wid] + (size_t)row * (size_t)C;

    float t1 = -CUDART_INF_F, t2 = -CUDART_INF_F;

    const int nv4 = C >> 2;                 // C=1000 -> 250 float4 per row
    const float4* p4 = (const float4*)p;    // 4000B row pitch, 16B aligned
    #pragma unroll 8
    for (int i = lane; i < nv4; i += 32) {
        float4 v = p4[i];
        t2 = fmaxf(t2, fminf(t1, v.x)); t1 = fmaxf(t1, v.x);
        t2 = fmaxf(t2, fminf(t1, v.y)); t1 = fmaxf(t1, v.y);
        t2 = fmaxf(t2, fminf(t1, v.z)); t1 = fmaxf(t1, v.z);
        t2 = fmaxf(t2, fminf(t1, v.w)); t1 = fmaxf(t1, v.w);
    }
    // tail for C % 4 != 0 (not hit at C=1000)
    for (int i = (nv4 << 2) + lane; i < C; i += 32) {
        float v = p[i];
        t2 = fmaxf(t2, fminf(t1, v)); t1 = fmaxf(t1, v);
    }

    // warp top-2 reduction
    #pragma unroll
    for (int off = 16; off; off >>= 1) {
        float u1 = __shfl_down_sync(0xFFFFFFFFu, t1, off);
        float u2 = __shfl_down_sync(0xFFFFFFFFu, t2, off);
        t2 = fmaxf(fmaxf(t2, u2), fminf(t1, u1));
        t1 = fmaxf(t1, u1);
    }

    if (lane == 0) {
        float tval = __ldg(p + targets[row]);
        s_margin[wid] = (tval == t1) ? (t1 - t2) : 0.0f;
        s_top1[wid]   = t1;
    }
    __syncthreads();

    if (threadIdx.x == 0) {
        // row max over heads 1..6 (no atomics, plain overwrite)
        float bm = s_top1[0];
        #pragma unroll
        for (int h = 1; h < 6; ++h) bm = fmaxf(bm, s_top1[h]);
        g_blockmax[row] = bm;

        // 7-way softmax of margins / TEMPERATURE (=2)
        float m[7], mx = -CUDART_INF_F;
        #pragma unroll
        for (int h = 0; h < 7; ++h) { m[h] = s_margin[h] * 0.5f; mx = fmaxf(mx, m[h]); }
        float e[7], sum = 0.0f;
        #pragma unroll
        for (int h = 0; h < 7; ++h) { e[h] = __expf(m[h] - mx); sum += e[h]; }
        float inv = 1.0f / sum;
        float* o = out_thresh + (size_t)row * 7;
        #pragma unroll
        for (int h = 0; h < 7; ++h) o[h] = e[h] * inv;
    }
}

// Single-block reduction of g_blockmax[0..n) -> out[0]
__global__ __launch_bounds__(1024) void finalize_kernel(float* __restrict__ out, int n) {
    __shared__ float s[32];
    float m = -CUDART_INF_F;
    for (int i = threadIdx.x; i < n; i += 1024)
        m = fmaxf(m, g_blockmax[i]);
    #pragma unroll
    for (int off = 16; off; off >>= 1)
        m = fmaxf(m, __shfl_down_sync(0xFFFFFFFFu, m, off));
    if ((threadIdx.x & 31) == 0) s[threadIdx.x >> 5] = m;
    __syncthreads();
    if (threadIdx.x < 32) {
        m = s[threadIdx.x];
        #pragma unroll
        for (int off = 16; off; off >>= 1)
            m = fmaxf(m, __shfl_down_sync(0xFFFFFFFFu, m, off));
        if (threadIdx.x == 0) out[0] = m;
    }
}

extern "C" void kernel_launch(void* const* d_in, const int* in_sizes, int n_in,
                              void* d_out, int out_size) {
    const float* o1    = (const float*)d_in[0];
    const float* o2    = (const float*)d_in[1];
    const float* o3    = (const float*)d_in[2];
    const float* o4    = (const float*)d_in[3];
    const float* o5    = (const float*)d_in[4];
    const float* o6    = (const float*)d_in[5];
    const float* mimic = (const float*)d_in[6];
    const int*   tgt   = (const int*)d_in[7];

    const int N = in_sizes[7];            // 16384 rows
    const int C = in_sizes[0] / N;        // 1000 classes

    float* out = (float*)d_out;           // [0] = max_preds, [1..] = thresholds [N,7]

    margin_softmax_kernel<<<N, 224>>>(o1, o2, o3, o4, o5, o6, mimic, tgt, out + 1, C);
    finalize_kernel<<<1, 1024>>>(out, N);
}

// round 3
// speedup vs baseline: 1.7360x; 1.7360x over previous
#include <cuda_runtime.h>
#include <math_constants.h>

// Per-row max of heads 1..6 (every slot overwritten every call -> no init needed)
#define MAX_ROWS 65536
__device__ float g_blockmax[MAX_ROWS];

__device__ __forceinline__ void top2_update(float& t1, float& t2, float v) {
    t2 = fmaxf(t2, fminf(t1, v));
    t1 = fmaxf(t1, v);
}

// ---------------- specialized kernel: compile-time row length ----------------
// One block per row, 256 threads (8 warps; warp 7 idle). Warp h (0..6) scans
// head h's row with 8 fully-unrolled, compile-time-predicated LDG.128 (MLP=8).
template<int NV4>   // NV4 = C/4, C % 4 == 0
__global__ __launch_bounds__(256) void margin_softmax_fixed(
    const float* __restrict__ o1, const float* __restrict__ o2,
    const float* __restrict__ o3, const float* __restrict__ o4,
    const float* __restrict__ o5, const float* __restrict__ o6,
    const float* __restrict__ mimic,
    const int* __restrict__ targets,
    float* __restrict__ out_thresh,   // [N,7]
    int C)
{
    const int row  = blockIdx.x;
    const int wid  = threadIdx.x >> 5;
    const int lane = threadIdx.x & 31;

    __shared__ float s_margin[7];
    __shared__ float s_top1[7];

    if (wid < 7) {
        const float* heads[7] = {o1, o2, o3, o4, o5, o6, mimic};
        const float* p = heads[wid] + (size_t)row * (size_t)C;
        const float4* p4 = (const float4*)p;

        constexpr int K = (NV4 + 31) / 32;   // 8 for NV4=250
        float4 v[K];
        #pragma unroll
        for (int k = 0; k < K; ++k) {
            int idx = lane + 32 * k;
            if (32 * k + 31 < NV4 || idx < NV4)   // compile-time elision where possible
                v[k] = p4[idx];
            else
                v[k] = make_float4(-CUDART_INF_F, -CUDART_INF_F,
                                   -CUDART_INF_F, -CUDART_INF_F);
        }

        float t1 = -CUDART_INF_F, t2 = -CUDART_INF_F;
        #pragma unroll
        for (int k = 0; k < K; ++k) {
            top2_update(t1, t2, v[k].x);
            top2_update(t1, t2, v[k].y);
            top2_update(t1, t2, v[k].z);
            top2_update(t1, t2, v[k].w);
        }

        #pragma unroll
        for (int off = 16; off; off >>= 1) {
            float u1 = __shfl_down_sync(0xFFFFFFFFu, t1, off);
            float u2 = __shfl_down_sync(0xFFFFFFFFu, t2, off);
            t2 = fmaxf(fmaxf(t2, u2), fminf(t1, u1));
            t1 = fmaxf(t1, u1);
        }

        if (lane == 0) {
            float tval = __ldg(p + targets[row]);
            s_margin[wid] = (tval == t1) ? (t1 - t2) : 0.0f;
            s_top1[wid]   = t1;
        }
    }
    __syncthreads();

    if (threadIdx.x == 0) {
        float bm = s_top1[0];
        #pragma unroll
        for (int h = 1; h < 6; ++h) bm = fmaxf(bm, s_top1[h]);
        g_blockmax[row] = bm;

        float m[7], mx = -CUDART_INF_F;
        #pragma unroll
        for (int h = 0; h < 7; ++h) { m[h] = s_margin[h] * 0.5f; mx = fmaxf(mx, m[h]); }
        float e[7], sum = 0.0f;
        #pragma unroll
        for (int h = 0; h < 7; ++h) { e[h] = __expf(m[h] - mx); sum += e[h]; }
        float inv = 1.0f / sum;
        float* o = out_thresh + (size_t)row * 7;
        #pragma unroll
        for (int h = 0; h < 7; ++h) o[h] = e[h] * inv;
    }
}

// ---------------- generic fallback (R1 structure, known-good) ----------------
__global__ __launch_bounds__(256) void margin_softmax_generic(
    const float* __restrict__ o1, const float* __restrict__ o2,
    const float* __restrict__ o3, const float* __restrict__ o4,
    const float* __restrict__ o5, const float* __restrict__ o6,
    const float* __restrict__ mimic,
    const int* __restrict__ targets,
    float* __restrict__ out_thresh,
    int C)
{
    const int row  = blockIdx.x;
    const int wid  = threadIdx.x >> 5;
    const int lane = threadIdx.x & 31;

    __shared__ float s_margin[7];
    __shared__ float s_top1[7];

    if (wid < 7) {
        const float* heads[7] = {o1, o2, o3, o4, o5, o6, mimic};
        const float* p = heads[wid] + (size_t)row * (size_t)C;

        float t1 = -CUDART_INF_F, t2 = -CUDART_INF_F;
        const int nv4 = C >> 2;
        const float4* p4 = (const float4*)p;
        for (int i = lane; i < nv4; i += 32) {
            float4 v = p4[i];
            top2_update(t1, t2, v.x); top2_update(t1, t2, v.y);
            top2_update(t1, t2, v.z); top2_update(t1, t2, v.w);
        }
        for (int i = (nv4 << 2) + lane; i < C; i += 32)
            top2_update(t1, t2, p[i]);

        #pragma unroll
        for (int off = 16; off; off >>= 1) {
            float u1 = __shfl_down_sync(0xFFFFFFFFu, t1, off);
            float u2 = __shfl_down_sync(0xFFFFFFFFu, t2, off);
            t2 = fmaxf(fmaxf(t2, u2), fminf(t1, u1));
            t1 = fmaxf(t1, u1);
        }

        if (lane == 0) {
            float tval = __ldg(p + targets[row]);
            s_margin[wid] = (tval == t1) ? (t1 - t2) : 0.0f;
            s_top1[wid]   = t1;
        }
    }
    __syncthreads();

    if (threadIdx.x == 0) {
        float bm = s_top1[0];
        #pragma unroll
        for (int h = 1; h < 6; ++h) bm = fmaxf(bm, s_top1[h]);
        g_blockmax[row] = bm;

        float m[7], mx = -CUDART_INF_F;
        #pragma unroll
        for (int h = 0; h < 7; ++h) { m[h] = s_margin[h] * 0.5f; mx = fmaxf(mx, m[h]); }
        float e[7], sum = 0.0f;
        #pragma unroll
        for (int h = 0; h < 7; ++h) { e[h] = __expf(m[h] - mx); sum += e[h]; }
        float inv = 1.0f / sum;
        float* o = out_thresh + (size_t)row * 7;
        #pragma unroll
        for (int h = 0; h < 7; ++h) o[h] = e[h] * inv;
    }
}

// Single-block float4 reduction of g_blockmax[0..n) -> out[0]
__global__ __launch_bounds__(1024) void finalize_kernel(float* __restrict__ out, int n) {
    __shared__ float s[32];
    float m = -CUDART_INF_F;
    const int nv4 = n >> 2;
    const float4* p4 = (const float4*)g_blockmax;
    for (int i = threadIdx.x; i < nv4; i += 1024) {
        float4 v = p4[i];
        m = fmaxf(m, fmaxf(fmaxf(v.x, v.y), fmaxf(v.z, v.w)));
    }
    for (int i = (nv4 << 2) + threadIdx.x; i < n; i += 1024)
        m = fmaxf(m, g_blockmax[i]);
    #pragma unroll
    for (int off = 16; off; off >>= 1)
        m = fmaxf(m, __shfl_down_sync(0xFFFFFFFFu, m, off));
    if ((threadIdx.x & 31) == 0) s[threadIdx.x >> 5] = m;
    __syncthreads();
    if (threadIdx.x < 32) {
        m = (threadIdx.x < 32) ? s[threadIdx.x] : -CUDART_INF_F;
        #pragma unroll
        for (int off = 16; off; off >>= 1)
            m = fmaxf(m, __shfl_down_sync(0xFFFFFFFFu, m, off));
        if (threadIdx.x == 0) out[0] = m;
    }
}

extern "C" void kernel_launch(void* const* d_in, const int* in_sizes, int n_in,
                              void* d_out, int out_size) {
    const float* o1    = (const float*)d_in[0];
    const float* o2    = (const float*)d_in[1];
    const float* o3    = (const float*)d_in[2];
    const float* o4    = (const float*)d_in[3];
    const float* o5    = (const float*)d_in[4];
    const float* o6    = (const float*)d_in[5];
    const float* mimic = (const float*)d_in[6];
    const int*   tgt   = (const int*)d_in[7];

    const int N = in_sizes[7];            // 16384 rows
    const int C = in_sizes[0] / N;        // 1000 classes

    float* out = (float*)d_out;           // [0] = max_preds, [1..] = thresholds [N,7]

    if (C == 1000) {
        margin_softmax_fixed<250><<<N, 256>>>(o1, o2, o3, o4, o5, o6, mimic, tgt, out + 1, C);
    } else {
        margin_softmax_generic<<<N, 256>>>(o1, o2, o3, o4, o5, o6, mimic, tgt, out + 1, C);
    }
    finalize_kernel<<<1, 1024>>>(out, N);
}